// round 9
// baseline (speedup 1.0000x reference)
#include <cuda_runtime.h>
#include <cuda_fp16.h>
#include <cstdint>

#define NN 100000
#define NN_PAD 100096
#define EE 1600000
#define NEDGE (EE + NN)
#define HH 128
#define GG 64
#define OUTD 32

// ---------------- scratch (device globals; no allocation allowed) ------------
__device__ int    g_deg[NN];
__device__ float  g_dinv[NN];
__device__ int    g_rowoff[NN + 1];
__device__ int    g_cursor[NN];
__device__ int2   g_cw[NEDGE];                    // packed (col, w bits)
__device__ float  g_bufB[(size_t)NN * HH];        // layer-3 agg output (head input)
__device__ __half g_half[(size_t)NN * HH];        // fp16 GEMM output for gather
__device__ uint2  g_Aimg[(size_t)NN_PAD * 32];    // A fp16 fragment-permuted cells {w, w+4}
__device__ uint4  g_Wiv[3 * 4608];                // W^T fp16 cells {hi_w,hi_w4,lo_w,lo_w4}, [128][36]
__device__ int    g_gcnt[GG];
__device__ int    g_goff[GG + 1];
__device__ int    g_part[128];

// ---------------- init + split x into permuted fp16 A image --------------------
__global__ void k_init(const float* __restrict__ x) {
    int idx = blockIdx.x * blockDim.x + threadIdx.x;   // NN*32 tasks
    if (idx < NN) { g_deg[idx] = 1; g_cursor[idx] = 0; }
    if (idx < GG) g_gcnt[idx] = 0;
    if (idx < NN * 32) {
        int row = idx >> 5, c = idx & 31;
        int w = ((c >> 2) << 3) + (c & 3);             // word index kk*8+q
        const float* xr = x + (size_t)row * 128;
        float2 p = *(const float2*)(xr + 2 * w);
        float2 s = *(const float2*)(xr + 2 * w + 8);
        __half2 hp = __floats2half2_rn(p.x, p.y);
        __half2 hs = __floats2half2_rn(s.x, s.y);
        g_Aimg[(size_t)row * 32 + c] = make_uint2(*(unsigned*)&hp, *(unsigned*)&hs);
    }
}

// degree histogram over dst + per-graph node counts (fused)
__global__ void k_count(const int* __restrict__ ei, const int* __restrict__ batch) {
    int e = blockIdx.x * blockDim.x + threadIdx.x;
    if (e < EE) atomicAdd(&g_deg[ei[EE + e]], 1);
    if (e < NN) atomicAdd(&g_gcnt[batch[e]], 1);
}

// ---------------- W -> transposed fp16 {hi,lo} cell image, stride 36 -----------
__global__ void k_prepW(const float* __restrict__ W1, const float* __restrict__ W2,
                        const float* __restrict__ W3) {
    const float* Ws[3] = {W1, W2, W3};
    int l = blockIdx.x;
    const float* W = Ws[l];
    uint4* dst = g_Wiv + l * 4608;
#pragma unroll
    for (int it = 0; it < 16; it++) {
        int idx = it * 256 + threadIdx.x;      // 4096 = (n, cell)
        int n = idx >> 5, c = idx & 31;
        int w = ((c >> 2) << 3) + (c & 3);
        int k0 = 2 * w;
        float wa = W[(size_t)k0 * 128 + n];
        float wb = W[(size_t)(k0 + 1) * 128 + n];
        float wc = W[(size_t)(k0 + 8) * 128 + n];
        float wd = W[(size_t)(k0 + 9) * 128 + n];
        __half2 hab = __floats2half2_rn(wa, wb);
        __half2 hcd = __floats2half2_rn(wc, wd);
        __half2 lab = __floats2half2_rn(wa - __low2float(hab), wb - __high2float(hab));
        __half2 lcd = __floats2half2_rn(wc - __low2float(hcd), wd - __high2float(hcd));
        uint4 cell;
        cell.x = *(unsigned*)&hab; cell.y = *(unsigned*)&hcd;
        cell.z = *(unsigned*)&lab; cell.w = *(unsigned*)&lcd;
        dst[n * 36 + c] = cell;
    }
}

// ---------------- scans (dinv fused into part; goff fused into mid) ------------
#define SCAN_CHUNK 1024
#define SCAN_PARTS ((NN + SCAN_CHUNK - 1) / SCAN_CHUNK)

__global__ void k_scan_part() {
    __shared__ int s[256];
    int base = blockIdx.x * SCAN_CHUNK;
    int t = threadIdx.x;
    int sum = 0;
#pragma unroll
    for (int j = 0; j < 4; j++) {
        int i = base + t + j * 256;
        if (i < NN) {
            int d = g_deg[i];
            sum += d;
            g_dinv[i] = rsqrtf((float)d);
        }
    }
    s[t] = sum; __syncthreads();
    for (int off = 128; off; off >>= 1) {
        if (t < off) s[t] += s[t + off];
        __syncthreads();
    }
    if (t == 0) g_part[blockIdx.x] = s[0];
}

__global__ void k_scan_mid() {
    int run = 0;
#pragma unroll
    for (int p = 0; p < SCAN_PARTS; p++) {
        int v = g_part[p];
        g_part[p] = run;
        run += v;
    }
    g_rowoff[NN] = run;
    int g = 0;
#pragma unroll
    for (int q = 0; q < GG; q++) {
        g_goff[q] = g;
        g += g_gcnt[q];
    }
    g_goff[GG] = g;
}

__global__ void k_scan_final() {
    __shared__ int s[SCAN_CHUNK];
    int t = threadIdx.x;
    int i = blockIdx.x * SCAN_CHUNK + t;
    int v = (i < NN) ? g_deg[i] : 0;
    s[t] = v; __syncthreads();
    for (int off = 1; off < SCAN_CHUNK; off <<= 1) {
        int x = (t >= off) ? s[t - off] : 0;
        __syncthreads();
        s[t] += x;
        __syncthreads();
    }
    if (i < NN) g_rowoff[i] = g_part[blockIdx.x] + s[t] - v;
}

__global__ void k_fill(const int* __restrict__ ei) {
    int idx = blockIdx.x * blockDim.x + threadIdx.x;
    if (idx >= NEDGE) return;
    int s, d;
    if (idx < EE) { s = ei[idx]; d = ei[EE + idx]; }
    else          { s = d = idx - EE; }
    int pos = g_rowoff[d] + atomicAdd(&g_cursor[d], 1);
    float w = g_dinv[s] * g_dinv[d];
    g_cw[pos] = make_int2(s, __float_as_int(w));
}

// ---------------- tensor-core GEMM (mma.sync fp16, 2-pass split W) -------------
// block = 128x128 tile, 8 warps as 2 row-groups x 4 col-groups, warp = 64x32.
// Each B cell LDS.128 feeds 8 MMAs (4 m16-blocks x 2 passes).
#define GSM 73728   // 128 rows * 36 uint4 * 16 B

#define MMA_F16(C, A0, A1, A2, A3, B0, B1) \
    asm volatile("mma.sync.aligned.m16n8k16.row.col.f32.f16.f16.f32 " \
                 "{%0,%1,%2,%3}, {%4,%5,%6,%7}, {%8,%9}, {%0,%1,%2,%3};" \
                 : "+f"((C)[0]), "+f"((C)[1]), "+f"((C)[2]), "+f"((C)[3]) \
                 : "r"(A0), "r"(A1), "r"(A2), "r"(A3), "r"(B0), "r"(B1))

__global__ void __launch_bounds__(256, 2) k_gemm_mma(int layer) {
    extern __shared__ char smem[];
    int tid = threadIdx.x;
    int row0 = blockIdx.x << 7;

    // stage B cell image: 4608 uint4 = 72 KB
    {
        const uint4* src = g_Wiv + layer * 4608;
        uint4* dst = (uint4*)smem;
#pragma unroll
        for (int it = 0; it < 18; it++) {
            int i = it * 256 + tid;
            dst[i] = __ldg(&src[i]);
        }
    }
    __syncthreads();

    const uint4* pB = (const uint4*)smem;
    const uint2* pA = g_Aimg;

    int lane = tid & 31, warp = tid >> 5;
    int rq = lane >> 2;        // 0..7
    int q = lane & 3;          // 0..3
    int rg = warp & 1, cgi = warp >> 1;
    int wrow = row0 + rg * 64;
    int ncol0 = cgi * 32;

    float c[4][4][4];          // [m16 block][n8 block][frag]
#pragma unroll
    for (int mb = 0; mb < 4; mb++)
#pragma unroll
        for (int t = 0; t < 4; t++)
#pragma unroll
            for (int j = 0; j < 4; j++) c[mb][t][j] = 0.f;

    size_t a0 = (size_t)(wrow + rq) * 32 + q;   // mb stride 512, V offset 256
    uint2 U[4], V[4];
#pragma unroll
    for (int mb = 0; mb < 4; mb++) {
        U[mb] = pA[a0 + mb * 512];
        V[mb] = pA[a0 + mb * 512 + 256];
    }

    const uint4* bBase = pB + (ncol0 + rq) * 36 + q;

#pragma unroll
    for (int kk = 0; kk < 8; kk++) {
        uint2 NU[4], NV[4];
        if (kk < 7) {
            size_t an = a0 + (kk + 1) * 4;
#pragma unroll
            for (int mb = 0; mb < 4; mb++) {
                NU[mb] = pA[an + mb * 512];
                NV[mb] = pA[an + mb * 512 + 256];
            }
        }
        const uint4* bp = bBase + kk * 4;
#pragma unroll
        for (int t = 0; t < 4; t++) {
            uint4 B = bp[t * 8 * 36];
            MMA_F16(c[0][t], U[0].x, V[0].x, U[0].y, V[0].y, B.x, B.y);
            MMA_F16(c[1][t], U[1].x, V[1].x, U[1].y, V[1].y, B.x, B.y);
            MMA_F16(c[2][t], U[2].x, V[2].x, U[2].y, V[2].y, B.x, B.y);
            MMA_F16(c[3][t], U[3].x, V[3].x, U[3].y, V[3].y, B.x, B.y);
            MMA_F16(c[0][t], U[0].x, V[0].x, U[0].y, V[0].y, B.z, B.w);
            MMA_F16(c[1][t], U[1].x, V[1].x, U[1].y, V[1].y, B.z, B.w);
            MMA_F16(c[2][t], U[2].x, V[2].x, U[2].y, V[2].y, B.z, B.w);
            MMA_F16(c[3][t], U[3].x, V[3].x, U[3].y, V[3].y, B.z, B.w);
        }
#pragma unroll
        for (int mb = 0; mb < 4; mb++) { U[mb] = NU[mb]; V[mb] = NV[mb]; }
    }

    // epilogue: fp16 stores straight from fragments
    unsigned short* gh = (unsigned short*)g_half;
#pragma unroll
    for (int mb = 0; mb < 4; mb++) {
        int r1 = wrow + mb * 16 + rq, r2 = r1 + 8;
#pragma unroll
        for (int t = 0; t < 4; t++) {
            int col = ncol0 + t * 8 + q * 2;
            if (r1 < NN) {
                __half2 h = __floats2half2_rn(c[mb][t][0], c[mb][t][1]);
                *(unsigned*)(gh + (size_t)r1 * 128 + col) = *(unsigned*)&h;
            }
            if (r2 < NN) {
                __half2 h = __floats2half2_rn(c[mb][t][2], c[mb][t][3]);
                *(unsigned*)(gh + (size_t)r2 * 128 + col) = *(unsigned*)&h;
            }
        }
    }
}

// ---------------- CSR aggregation from fp16 features ----------------------------
// mode 0: relu, write fp16 A image (GEMM input). mode 1: no relu, write fp32 bufB.
__global__ void k_agg_h(const float* __restrict__ bias, int mode) {
    int row = (blockIdx.x * blockDim.x + threadIdx.x) >> 5;
    int lane = threadIdx.x & 31;
    if (row >= NN) return;
    int beg = g_rowoff[row];
    int end = g_rowoff[row + 1];
    const uint2* T = (const uint2*)g_half;
    float4 acc0 = make_float4(0.f, 0.f, 0.f, 0.f);
    float4 acc1 = make_float4(0.f, 0.f, 0.f, 0.f);
    int e = beg;
    for (; e + 3 < end; e += 4) {
        int2 cw0 = g_cw[e],     cw1 = g_cw[e + 1];
        int2 cw2 = g_cw[e + 2], cw3 = g_cw[e + 3];
        uint2 u0 = __ldg(&T[(size_t)cw0.x * 32 + lane]);
        uint2 u1 = __ldg(&T[(size_t)cw1.x * 32 + lane]);
        uint2 u2 = __ldg(&T[(size_t)cw2.x * 32 + lane]);
        uint2 u3 = __ldg(&T[(size_t)cw3.x * 32 + lane]);
        float w0 = __int_as_float(cw0.y), w1 = __int_as_float(cw1.y);
        float w2 = __int_as_float(cw2.y), w3 = __int_as_float(cw3.y);
        float2 a0 = __half22float2(*(__half2*)&u0.x), b0 = __half22float2(*(__half2*)&u0.y);
        float2 a1 = __half22float2(*(__half2*)&u1.x), b1 = __half22float2(*(__half2*)&u1.y);
        float2 a2 = __half22float2(*(__half2*)&u2.x), b2 = __half22float2(*(__half2*)&u2.y);
        float2 a3 = __half22float2(*(__half2*)&u3.x), b3 = __half22float2(*(__half2*)&u3.y);
        acc0.x = fmaf(w0, a0.x, acc0.x); acc0.y = fmaf(w0, a0.y, acc0.y);
        acc0.z = fmaf(w0, b0.x, acc0.z); acc0.w = fmaf(w0, b0.y, acc0.w);
        acc1.x = fmaf(w1, a1.x, acc1.x); acc1.y = fmaf(w1, a1.y, acc1.y);
        acc1.z = fmaf(w1, b1.x, acc1.z); acc1.w = fmaf(w1, b1.y, acc1.w);
        acc0.x = fmaf(w2, a2.x, acc0.x); acc0.y = fmaf(w2, a2.y, acc0.y);
        acc0.z = fmaf(w2, b2.x, acc0.z); acc0.w = fmaf(w2, b2.y, acc0.w);
        acc1.x = fmaf(w3, a3.x, acc1.x); acc1.y = fmaf(w3, a3.y, acc1.y);
        acc1.z = fmaf(w3, b3.x, acc1.z); acc1.w = fmaf(w3, b3.y, acc1.w);
    }
    for (; e < end; e++) {
        int2 cw = g_cw[e];
        float w = __int_as_float(cw.y);
        uint2 u = __ldg(&T[(size_t)cw.x * 32 + lane]);
        float2 a = __half22float2(*(__half2*)&u.x);
        float2 b = __half22float2(*(__half2*)&u.y);
        acc0.x = fmaf(w, a.x, acc0.x); acc0.y = fmaf(w, a.y, acc0.y);
        acc0.z = fmaf(w, b.x, acc0.z); acc0.w = fmaf(w, b.y, acc0.w);
    }
    float4 b4 = ((const float4*)bias)[lane];
    float4 r;
    r.x = acc0.x + acc1.x + b4.x;
    r.y = acc0.y + acc1.y + b4.y;
    r.z = acc0.z + acc1.z + b4.z;
    r.w = acc0.w + acc1.w + b4.w;
    if (mode == 0) {
        r.x = fmaxf(r.x, 0.f); r.y = fmaxf(r.y, 0.f);
        r.z = fmaxf(r.z, 0.f); r.w = fmaxf(r.w, 0.f);
        // assemble this lane's A-image cell via shfl (lane = cell index)
        __half2 h01 = __floats2half2_rn(r.x, r.y);
        __half2 h23 = __floats2half2_rn(r.z, r.w);
        unsigned w01 = *(unsigned*)&h01, w23 = *(unsigned*)&h23;
        int kk = lane >> 2, q = lane & 3;
        int lA = 4 * kk + (q >> 1);
        int lB = lA + 2;
        unsigned a01 = __shfl_sync(0xFFFFFFFFu, w01, lA);
        unsigned a23 = __shfl_sync(0xFFFFFFFFu, w23, lA);
        unsigned b01 = __shfl_sync(0xFFFFFFFFu, w01, lB);
        unsigned b23 = __shfl_sync(0xFFFFFFFFu, w23, lB);
        unsigned wa = (q & 1) ? a23 : a01;
        unsigned wb = (q & 1) ? b23 : b01;
        g_Aimg[(size_t)row * 32 + lane] = make_uint2(wa, wb);
    } else {
        ((float4*)g_bufB)[(size_t)row * 32 + lane] = r;
    }
}

// ---------------- fused pooling + MLP head: one block per graph ----------------
__global__ void k_head(const float* __restrict__ Wo1, const float* __restrict__ bo1,
                       const float* __restrict__ Wo2, const float* __restrict__ bo2,
                       float* __restrict__ out) {
    __shared__ float ps[256];
    __shared__ float zs[64];
    int g = blockIdx.x;
    int t = threadIdx.x;
    int start = g_goff[g];
    int end = g_goff[g + 1];
    int col = t & 127, half = t >> 7;
    float sum = 0.f;
    for (int i = start + half; i < end; i += 2)
        sum += g_bufB[(size_t)i * 128 + col];
    ps[t] = sum;
    __syncthreads();
    float inv = 1.0f / fmaxf((float)(end - start), 1.0f);
    if (t < 128) ps[t] = (ps[t] + ps[t + 128]) * inv;
    __syncthreads();
    if (t < 64) {
        float z = bo1[t];
#pragma unroll 8
        for (int k = 0; k < 128; k++) z = fmaf(ps[k], Wo1[k * 64 + t], z);
        zs[t] = fmaxf(z, 0.f);
    }
    __syncthreads();
    if (t < OUTD) {
        float o = bo2[t];
#pragma unroll 8
        for (int j = 0; j < 64; j++) o = fmaf(zs[j], Wo2[j * 32 + t], o);
        out[g * OUTD + t] = o;
    }
}

// ---------------- launch ------------------------------------------------------------
extern "C" void kernel_launch(void* const* d_in, const int* in_sizes, int n_in,
                              void* d_out, int out_size) {
    const float* x    = (const float*)d_in[0];
    const int*   ei   = (const int*)d_in[1];
    const int*   batch= (const int*)d_in[2];
    const float* W1   = (const float*)d_in[3];
    const float* b1   = (const float*)d_in[4];
    const float* W2   = (const float*)d_in[5];
    const float* b2   = (const float*)d_in[6];
    const float* W3   = (const float*)d_in[7];
    const float* b3   = (const float*)d_in[8];
    const float* Wo1  = (const float*)d_in[9];
    const float* bo1  = (const float*)d_in[10];
    const float* Wo2  = (const float*)d_in[11];
    const float* bo2  = (const float*)d_in[12];
    float* out = (float*)d_out;

    cudaFuncSetAttribute(k_gemm_mma, cudaFuncAttributeMaxDynamicSharedMemorySize, GSM);

    const int GEMM_BLOCKS = (NN + 127) / 128;   // 782 -> covers NN_PAD rows
    const int AGG_BLOCKS  = (NN + 7) / 8;

    k_init<<<(NN * 32 + 255) / 256, 256>>>(x);           // 0: init + split x
    k_count<<<(EE + 255) / 256, 256>>>(ei, batch);       // 1
    k_prepW<<<3, 256>>>(W1, W2, W3);                     // 2
    k_gemm_mma<<<GEMM_BLOCKS, 256, GSM>>>(0);            // 3  <- ncu slot
    k_scan_part<<<SCAN_PARTS, 256>>>();                  // 4
    k_scan_mid<<<1, 1>>>();                              // 5
    k_scan_final<<<SCAN_PARTS, SCAN_CHUNK>>>();          // 6
    k_fill<<<(NEDGE + 255) / 256, 256>>>(ei);            // 7

    k_agg_h<<<AGG_BLOCKS, 256>>>(b1, 0);                 // 8
    k_gemm_mma<<<GEMM_BLOCKS, 256, GSM>>>(1);            // 9
    k_agg_h<<<AGG_BLOCKS, 256>>>(b2, 0);                 // 10
    k_gemm_mma<<<GEMM_BLOCKS, 256, GSM>>>(2);            // 11
    k_agg_h<<<AGG_BLOCKS, 256>>>(b3, 1);                 // 12

    k_head<<<GG, 256>>>(Wo1, bo1, Wo2, bo2, out);        // 13
}

// round 10
// speedup vs baseline: 1.1477x; 1.1477x over previous
#include <cuda_runtime.h>
#include <cuda_fp16.h>
#include <cstdint>

#define NN 100000
#define NN_PAD 100096
#define EE 1600000
#define NEDGE (EE + NN)
#define HH 128
#define GG 64
#define OUTD 32

// ---------------- scratch (device globals; no allocation allowed) ------------
__device__ int    g_deg[NN];
__device__ float  g_dinv[NN];
__device__ int    g_rowoff[NN + 1];
__device__ int    g_cursor[NN];
__device__ int2   g_cw[NEDGE];                    // packed (col, w bits)
__device__ float  g_bufB[(size_t)NN * HH];        // layer-3 agg output (pool input)
__device__ __half g_half[(size_t)NN * HH];        // fp16 GEMM output for gather
__device__ uint2  g_Aimg[(size_t)NN_PAD * 32];    // A fp16 fragment-permuted cells {w, w+4}
__device__ uint4  g_Wiv[3 * 2560];                // W^T fp16 paired-kk cells, [128][20]
__device__ float  g_pool[GG * HH];
__device__ int    g_gcnt[GG];
__device__ int    g_goff[GG + 1];
__device__ int    g_part[128];

// ---------------- init + split x into permuted fp16 A image --------------------
__global__ void k_init(const float* __restrict__ x) {
    int idx = blockIdx.x * blockDim.x + threadIdx.x;   // NN*32 tasks
    if (idx < NN) { g_deg[idx] = 1; g_cursor[idx] = 0; }
    if (idx < GG) g_gcnt[idx] = 0;
    if (idx < GG * HH) g_pool[idx] = 0.0f;
    if (idx < NN * 32) {
        int row = idx >> 5, c = idx & 31;
        int w = ((c >> 2) << 3) + (c & 3);             // word index kk*8+q
        const float* xr = x + (size_t)row * 128;
        float2 p = *(const float2*)(xr + 2 * w);
        float2 s = *(const float2*)(xr + 2 * w + 8);
        __half2 hp = __floats2half2_rn(p.x, p.y);
        __half2 hs = __floats2half2_rn(s.x, s.y);
        g_Aimg[(size_t)row * 32 + c] = make_uint2(*(unsigned*)&hp, *(unsigned*)&hs);
    }
}

// degree histogram over dst + per-graph node counts (fused)
__global__ void k_count(const int* __restrict__ ei, const int* __restrict__ batch) {
    int e = blockIdx.x * blockDim.x + threadIdx.x;
    if (e < EE) atomicAdd(&g_deg[ei[EE + e]], 1);
    if (e < NN) atomicAdd(&g_gcnt[batch[e]], 1);
}

// ---------------- W -> transposed fp16 paired-kk cell image, stride 20 ---------
// cell (n, j, q) = {halves(k=32j+2q,+1), halves(+8,+9), halves(k=32j+16+2q,+1), halves(+8,+9)}
__global__ void k_prepW(const float* __restrict__ W1, const float* __restrict__ W2,
                        const float* __restrict__ W3) {
    const float* Ws[3] = {W1, W2, W3};
    int l = blockIdx.x;
    const float* W = Ws[l];
    uint4* dst = g_Wiv + l * 2560;
#pragma unroll
    for (int it = 0; it < 8; it++) {
        int idx = it * 256 + threadIdx.x;      // 2048 = (n, cell)
        int n = idx >> 4, c = idx & 15;
        int j = c >> 2, q = c & 3;
        int ka = 32 * j + 2 * q;
        int kb = ka + 16;
        __half2 x0 = __floats2half2_rn(W[(size_t)ka * 128 + n],       W[(size_t)(ka + 1) * 128 + n]);
        __half2 y0 = __floats2half2_rn(W[(size_t)(ka + 8) * 128 + n], W[(size_t)(ka + 9) * 128 + n]);
        __half2 z0 = __floats2half2_rn(W[(size_t)kb * 128 + n],       W[(size_t)(kb + 1) * 128 + n]);
        __half2 w0 = __floats2half2_rn(W[(size_t)(kb + 8) * 128 + n], W[(size_t)(kb + 9) * 128 + n]);
        uint4 cell;
        cell.x = *(unsigned*)&x0; cell.y = *(unsigned*)&y0;
        cell.z = *(unsigned*)&z0; cell.w = *(unsigned*)&w0;
        dst[n * 20 + c] = cell;
    }
}

// ---------------- scans (dinv fused into part; goff fused into mid) ------------
#define SCAN_CHUNK 1024
#define SCAN_PARTS ((NN + SCAN_CHUNK - 1) / SCAN_CHUNK)

__global__ void k_scan_part() {
    __shared__ int s[256];
    int base = blockIdx.x * SCAN_CHUNK;
    int t = threadIdx.x;
    int sum = 0;
#pragma unroll
    for (int j = 0; j < 4; j++) {
        int i = base + t + j * 256;
        if (i < NN) {
            int d = g_deg[i];
            sum += d;
            g_dinv[i] = rsqrtf((float)d);
        }
    }
    s[t] = sum; __syncthreads();
    for (int off = 128; off; off >>= 1) {
        if (t < off) s[t] += s[t + off];
        __syncthreads();
    }
    if (t == 0) g_part[blockIdx.x] = s[0];
}

__global__ void k_scan_mid() {
    int run = 0;
#pragma unroll
    for (int p = 0; p < SCAN_PARTS; p++) {
        int v = g_part[p];
        g_part[p] = run;
        run += v;
    }
    g_rowoff[NN] = run;
    int g = 0;
#pragma unroll
    for (int q = 0; q < GG; q++) {
        g_goff[q] = g;
        g += g_gcnt[q];
    }
    g_goff[GG] = g;
}

__global__ void k_scan_final() {
    __shared__ int s[SCAN_CHUNK];
    int t = threadIdx.x;
    int i = blockIdx.x * SCAN_CHUNK + t;
    int v = (i < NN) ? g_deg[i] : 0;
    s[t] = v; __syncthreads();
    for (int off = 1; off < SCAN_CHUNK; off <<= 1) {
        int x = (t >= off) ? s[t - off] : 0;
        __syncthreads();
        s[t] += x;
        __syncthreads();
    }
    if (i < NN) g_rowoff[i] = g_part[blockIdx.x] + s[t] - v;
}

__global__ void k_fill(const int* __restrict__ ei) {
    int idx = blockIdx.x * blockDim.x + threadIdx.x;
    if (idx >= NEDGE) return;
    int s, d;
    if (idx < EE) { s = ei[idx]; d = ei[EE + idx]; }
    else          { s = d = idx - EE; }
    int pos = g_rowoff[d] + atomicAdd(&g_cursor[d], 1);
    float w = g_dinv[s] * g_dinv[d];
    g_cw[pos] = make_int2(s, __float_as_int(w));
}

// ---------------- tensor-core GEMM (mma.sync fp16, single-pass W) --------------
// block = 128x128 tile, 8 warps as 4 row-groups x 2 col-groups, warp = 32x64.
// B cells pack 2 adjacent kk blocks per uint4; stride 20 uint4 (conflict-free).
#define GSM 40960   // 128 rows * 20 uint4 * 16 B

#define MMA_F16(C, A0, A1, A2, A3, B0, B1) \
    asm volatile("mma.sync.aligned.m16n8k16.row.col.f32.f16.f16.f32 " \
                 "{%0,%1,%2,%3}, {%4,%5,%6,%7}, {%8,%9}, {%0,%1,%2,%3};" \
                 : "+f"((C)[0]), "+f"((C)[1]), "+f"((C)[2]), "+f"((C)[3]) \
                 : "r"(A0), "r"(A1), "r"(A2), "r"(A3), "r"(B0), "r"(B1))

__global__ void __launch_bounds__(256, 2) k_gemm_mma(int layer) {
    extern __shared__ char smem[];
    int tid = threadIdx.x;
    int row0 = blockIdx.x << 7;

    // stage B cell image: 2560 uint4 = 40 KB
    {
        const uint4* src = g_Wiv + layer * 2560;
        uint4* dst = (uint4*)smem;
#pragma unroll
        for (int it = 0; it < 10; it++) {
            int i = it * 256 + tid;
            dst[i] = __ldg(&src[i]);
        }
    }
    __syncthreads();

    const uint4* pB = (const uint4*)smem;
    const uint2* pA = g_Aimg;

    int lane = tid & 31, warp = tid >> 5;
    int rq = lane >> 2;        // 0..7
    int q = lane & 3;          // 0..3
    int rg = warp >> 1, cg = warp & 1;
    int wrow = row0 + rg * 32;
    int ncol0 = cg * 64;

    float c[2][8][4];
#pragma unroll
    for (int rb = 0; rb < 2; rb++)
#pragma unroll
        for (int t = 0; t < 8; t++)
#pragma unroll
            for (int j = 0; j < 4; j++) c[rb][t][j] = 0.f;

    size_t a0 = (size_t)(wrow + rq) * 32 + q;   // A cell offset for kk: +kk*4
    // Acur[0..3] = kk_a cells rows {+0,+8,+16,+24}; [4..7] = kk_b cells
    uint2 Acur[8];
#pragma unroll
    for (int m = 0; m < 4; m++) {
        Acur[m]     = pA[a0 + m * 256];
        Acur[4 + m] = pA[a0 + 4 + m * 256];
    }

    const uint4* bBase = pB + (ncol0 + rq) * 20 + q;

#pragma unroll
    for (int j = 0; j < 4; j++) {
        uint2 Anxt[8];
        if (j < 3) {
            size_t an = a0 + (j + 1) * 8;
#pragma unroll
            for (int m = 0; m < 4; m++) {
                Anxt[m]     = pA[an + m * 256];
                Anxt[4 + m] = pA[an + 4 + m * 256];
            }
        }
        const uint4* bp = bBase + j * 4;
#pragma unroll
        for (int t = 0; t < 8; t++) {
            uint4 B = bp[t * 8 * 20];
            MMA_F16(c[0][t], Acur[0].x, Acur[1].x, Acur[0].y, Acur[1].y, B.x, B.y);
            MMA_F16(c[1][t], Acur[2].x, Acur[3].x, Acur[2].y, Acur[3].y, B.x, B.y);
            MMA_F16(c[0][t], Acur[4].x, Acur[5].x, Acur[4].y, Acur[5].y, B.z, B.w);
            MMA_F16(c[1][t], Acur[6].x, Acur[7].x, Acur[6].y, Acur[7].y, B.z, B.w);
        }
#pragma unroll
        for (int m = 0; m < 8; m++) Acur[m] = Anxt[m];
    }

    // epilogue: fp16 stores straight from fragments
    unsigned short* gh = (unsigned short*)g_half;
#pragma unroll
    for (int rb = 0; rb < 2; rb++) {
        int r1 = wrow + rb * 16 + rq, r2 = r1 + 8;
#pragma unroll
        for (int t = 0; t < 8; t++) {
            int col = ncol0 + t * 8 + q * 2;
            if (r1 < NN) {
                __half2 h = __floats2half2_rn(c[rb][t][0], c[rb][t][1]);
                *(unsigned*)(gh + (size_t)r1 * 128 + col) = *(unsigned*)&h;
            }
            if (r2 < NN) {
                __half2 h = __floats2half2_rn(c[rb][t][2], c[rb][t][3]);
                *(unsigned*)(gh + (size_t)r2 * 128 + col) = *(unsigned*)&h;
            }
        }
    }
}

// ---------------- CSR aggregation from fp16 features ----------------------------
// mode 0: relu, write fp16 A image (GEMM input). mode 1: no relu, write fp32 bufB.
__global__ void k_agg_h(const float* __restrict__ bias, int mode) {
    int row = (blockIdx.x * blockDim.x + threadIdx.x) >> 5;
    int lane = threadIdx.x & 31;
    if (row >= NN) return;
    int beg = g_rowoff[row];
    int end = g_rowoff[row + 1];
    const uint2* T = (const uint2*)g_half;
    float4 acc0 = make_float4(0.f, 0.f, 0.f, 0.f);
    float4 acc1 = make_float4(0.f, 0.f, 0.f, 0.f);
    int e = beg;
    for (; e + 3 < end; e += 4) {
        int2 cw0 = g_cw[e],     cw1 = g_cw[e + 1];
        int2 cw2 = g_cw[e + 2], cw3 = g_cw[e + 3];
        uint2 u0 = __ldg(&T[(size_t)cw0.x * 32 + lane]);
        uint2 u1 = __ldg(&T[(size_t)cw1.x * 32 + lane]);
        uint2 u2 = __ldg(&T[(size_t)cw2.x * 32 + lane]);
        uint2 u3 = __ldg(&T[(size_t)cw3.x * 32 + lane]);
        float w0 = __int_as_float(cw0.y), w1 = __int_as_float(cw1.y);
        float w2 = __int_as_float(cw2.y), w3 = __int_as_float(cw3.y);
        float2 a0 = __half22float2(*(__half2*)&u0.x), b0 = __half22float2(*(__half2*)&u0.y);
        float2 a1 = __half22float2(*(__half2*)&u1.x), b1 = __half22float2(*(__half2*)&u1.y);
        float2 a2 = __half22float2(*(__half2*)&u2.x), b2 = __half22float2(*(__half2*)&u2.y);
        float2 a3 = __half22float2(*(__half2*)&u3.x), b3 = __half22float2(*(__half2*)&u3.y);
        acc0.x = fmaf(w0, a0.x, acc0.x); acc0.y = fmaf(w0, a0.y, acc0.y);
        acc0.z = fmaf(w0, b0.x, acc0.z); acc0.w = fmaf(w0, b0.y, acc0.w);
        acc1.x = fmaf(w1, a1.x, acc1.x); acc1.y = fmaf(w1, a1.y, acc1.y);
        acc1.z = fmaf(w1, b1.x, acc1.z); acc1.w = fmaf(w1, b1.y, acc1.w);
        acc0.x = fmaf(w2, a2.x, acc0.x); acc0.y = fmaf(w2, a2.y, acc0.y);
        acc0.z = fmaf(w2, b2.x, acc0.z); acc0.w = fmaf(w2, b2.y, acc0.w);
        acc1.x = fmaf(w3, a3.x, acc1.x); acc1.y = fmaf(w3, a3.y, acc1.y);
        acc1.z = fmaf(w3, b3.x, acc1.z); acc1.w = fmaf(w3, b3.y, acc1.w);
    }
    for (; e < end; e++) {
        int2 cw = g_cw[e];
        float w = __int_as_float(cw.y);
        uint2 u = __ldg(&T[(size_t)cw.x * 32 + lane]);
        float2 a = __half22float2(*(__half2*)&u.x);
        float2 b = __half22float2(*(__half2*)&u.y);
        acc0.x = fmaf(w, a.x, acc0.x); acc0.y = fmaf(w, a.y, acc0.y);
        acc0.z = fmaf(w, b.x, acc0.z); acc0.w = fmaf(w, b.y, acc0.w);
    }
    float4 b4 = ((const float4*)bias)[lane];
    float4 r;
    r.x = acc0.x + acc1.x + b4.x;
    r.y = acc0.y + acc1.y + b4.y;
    r.z = acc0.z + acc1.z + b4.z;
    r.w = acc0.w + acc1.w + b4.w;
    if (mode == 0) {
        r.x = fmaxf(r.x, 0.f); r.y = fmaxf(r.y, 0.f);
        r.z = fmaxf(r.z, 0.f); r.w = fmaxf(r.w, 0.f);
        // assemble this lane's A-image cell via shfl (lane = cell index)
        __half2 h01 = __floats2half2_rn(r.x, r.y);
        __half2 h23 = __floats2half2_rn(r.z, r.w);
        unsigned w01 = *(unsigned*)&h01, w23 = *(unsigned*)&h23;
        int kk = lane >> 2, q = lane & 3;
        int lA = 4 * kk + (q >> 1);
        int lB = lA + 2;
        unsigned a01 = __shfl_sync(0xFFFFFFFFu, w01, lA);
        unsigned a23 = __shfl_sync(0xFFFFFFFFu, w23, lA);
        unsigned b01 = __shfl_sync(0xFFFFFFFFu, w01, lB);
        unsigned b23 = __shfl_sync(0xFFFFFFFFu, w23, lB);
        unsigned wa = (q & 1) ? a23 : a01;
        unsigned wb = (q & 1) ? b23 : b01;
        g_Aimg[(size_t)row * 32 + lane] = make_uint2(wa, wb);
    } else {
        ((float4*)g_bufB)[(size_t)row * 32 + lane] = r;
    }
}

// ---------------- pooling --------------------------------------------------------
__global__ void k_pool() {
    int g = blockIdx.x >> 3;
    int s = blockIdx.x & 7;
    int col = threadIdx.x;
    int start = g_goff[g];
    int cnt = g_goff[g + 1] - start;
    int chunk = (cnt + 7) >> 3;
    int lo = start + s * chunk;
    int hi = lo + chunk;
    int ge = start + cnt;
    if (hi > ge) hi = ge;
    float sum = 0.f;
    int i = lo;
    for (; i + 3 < hi; i += 4) {
        sum += g_bufB[(size_t)(i + 0) * 128 + col];
        sum += g_bufB[(size_t)(i + 1) * 128 + col];
        sum += g_bufB[(size_t)(i + 2) * 128 + col];
        sum += g_bufB[(size_t)(i + 3) * 128 + col];
    }
    for (; i < hi; i++) sum += g_bufB[(size_t)i * 128 + col];
    if (lo < hi) atomicAdd(&g_pool[g * 128 + col], sum);
}

// ---------------- MLP head --------------------------------------------------------
__global__ void k_mlp(const float* __restrict__ Wo1, const float* __restrict__ bo1,
                      const float* __restrict__ Wo2, const float* __restrict__ bo2,
                      float* __restrict__ out) {
    __shared__ float ps[128];
    __shared__ float zs[64];
    int g = blockIdx.x;
    int t = threadIdx.x;
    int cnt = g_goff[g + 1] - g_goff[g];
    float inv = 1.0f / fmaxf((float)cnt, 1.0f);
    ps[t]      = g_pool[g * 128 + t] * inv;
    ps[t + 64] = g_pool[g * 128 + t + 64] * inv;
    __syncthreads();
    float z = bo1[t];
#pragma unroll 8
    for (int k = 0; k < 128; k++) z = fmaf(ps[k], Wo1[k * 64 + t], z);
    zs[t] = fmaxf(z, 0.f);
    __syncthreads();
    if (t < OUTD) {
        float o = bo2[t];
#pragma unroll 8
        for (int j = 0; j < 64; j++) o = fmaf(zs[j], Wo2[j * 32 + t], o);
        out[g * OUTD + t] = o;
    }
}

// ---------------- launch ------------------------------------------------------------
extern "C" void kernel_launch(void* const* d_in, const int* in_sizes, int n_in,
                              void* d_out, int out_size) {
    const float* x    = (const float*)d_in[0];
    const int*   ei   = (const int*)d_in[1];
    const int*   batch= (const int*)d_in[2];
    const float* W1   = (const float*)d_in[3];
    const float* b1   = (const float*)d_in[4];
    const float* W2   = (const float*)d_in[5];
    const float* b2   = (const float*)d_in[6];
    const float* W3   = (const float*)d_in[7];
    const float* b3   = (const float*)d_in[8];
    const float* Wo1  = (const float*)d_in[9];
    const float* bo1  = (const float*)d_in[10];
    const float* Wo2  = (const float*)d_in[11];
    const float* bo2  = (const float*)d_in[12];
    float* out = (float*)d_out;

    cudaFuncSetAttribute(k_gemm_mma, cudaFuncAttributeMaxDynamicSharedMemorySize, GSM);

    const int GEMM_BLOCKS = (NN + 127) / 128;   // 782 -> covers NN_PAD rows
    const int AGG_BLOCKS  = (NN + 7) / 8;

    k_init<<<(NN * 32 + 255) / 256, 256>>>(x);           // 0: init + split x
    k_count<<<(EE + 255) / 256, 256>>>(ei, batch);       // 1
    k_prepW<<<3, 256>>>(W1, W2, W3);                     // 2
    k_gemm_mma<<<GEMM_BLOCKS, 256, GSM>>>(0);            // 3  <- ncu slot
    k_scan_part<<<SCAN_PARTS, 256>>>();                  // 4
    k_scan_mid<<<1, 1>>>();                              // 5
    k_scan_final<<<SCAN_PARTS, SCAN_CHUNK>>>();          // 6
    k_fill<<<(NEDGE + 255) / 256, 256>>>(ei);            // 7

    k_agg_h<<<AGG_BLOCKS, 256>>>(b1, 0);                 // 8
    k_gemm_mma<<<GEMM_BLOCKS, 256, GSM>>>(1);            // 9
    k_agg_h<<<AGG_BLOCKS, 256>>>(b2, 0);                 // 10
    k_gemm_mma<<<GEMM_BLOCKS, 256, GSM>>>(2);            // 11
    k_agg_h<<<AGG_BLOCKS, 256>>>(b3, 1);                 // 12

    k_pool<<<GG * 8, 128>>>();                           // 13
    k_mlp<<<GG, 64>>>(Wo1, bo1, Wo2, bo2, out);          // 14
}